// round 14
// baseline (speedup 1.0000x reference)
#include <cuda_runtime.h>
#include <cstdint>

// out = relu(x @ (gamma*W3 + W4)^T)
// (reference softmax is over a size-1 axis == 1.0 -> attention is identity on
//  the W3 branch; W1/W2 are dead inputs)
//
// TENSOR PATH, barrier-free mainloop. R12 (mma.sync + smem x ring) ran at
// ~2x its tensor floor because two block-wide __syncthreads per tile plus the
// A-split and STG epilogue serialized against HMMA. Here:
//  - each warp LDGs its own 10 x values per tile directly into registers
//    (no smem x, no barriers after init; B fragments are read-only smem),
//  - one-tile register prefetch hides DRAM latency inside each warp,
//  - K=20 handled exactly as 8+8+4 (m16n8k8 x2 + m16n8k4) -> 17% less
//    tensor work than 3x k8-with-padding.
// fp32 accuracy via 3-term tf32 split: D = xh*wh + xh*wl + xl*wh (~2^-22).
// Warp = (m_blk = wid&3 -> 16 rows, half = wid>>2 -> 13 n8-blocks).
// 296 persistent blocks x 256 threads (2 blocks/SM).

#define DICT 20
#define OUTC 200
#define NBLK 296
#define TPB 256
#define TILE 64
#define NBN 26                         // n8 blocks (208, last 8 masked)
#define NBW 13                         // n8 blocks per warp

__device__ __forceinline__ uint32_t cvt_tf32(float v) {
    uint32_t r;
    asm("cvt.rna.tf32.f32 %0, %1;" : "=r"(r) : "f"(v));
    return r;
}
__device__ __forceinline__ void mma8(float* c, const uint32_t* a,
                                     uint32_t b0, uint32_t b1) {
    asm volatile(
        "mma.sync.aligned.m16n8k8.row.col.f32.tf32.tf32.f32 "
        "{%0,%1,%2,%3}, {%4,%5,%6,%7}, {%8,%9}, {%0,%1,%2,%3};"
        : "+f"(c[0]), "+f"(c[1]), "+f"(c[2]), "+f"(c[3])
        : "r"(a[0]), "r"(a[1]), "r"(a[2]), "r"(a[3]), "r"(b0), "r"(b1));
}
__device__ __forceinline__ void mma4(float* c, uint32_t a0, uint32_t a1,
                                     uint32_t b0) {
    asm volatile(
        "mma.sync.aligned.m16n8k4.row.col.f32.tf32.tf32.f32 "
        "{%0,%1,%2,%3}, {%4,%5}, {%6}, {%0,%1,%2,%3};"
        : "+f"(c[0]), "+f"(c[1]), "+f"(c[2]), "+f"(c[3])
        : "r"(a0), "r"(a1), "r"(b0));
}
#define U(f) __float_as_uint(f)

__global__ __launch_bounds__(TPB, 2)
void fused_gemm_relu_mma(const float* __restrict__ x,
                         const float* __restrict__ W3,
                         const float* __restrict__ W4,
                         const float* __restrict__ gamma,
                         float* __restrict__ out, int ntiles) {
    // Packed B fragments (built once, then read-only):
    //  bf8[nb][kb][lane] = {bh(k0), bh(k1), bl(k0), bl(k1)}, k0=kb*8+lane%4
    //  bf4[nb][lane]     = {bh(16+lane%4), bl(16+lane%4)}
    __shared__ __align__(16) float4 bf8[NBN][2][32];   // 26624 B
    __shared__ __align__(8)  float2 bf4[NBN][32];      //  6656 B

    const int tid = threadIdx.x;
    const int wid = tid >> 5;
    const int lane = tid & 31;
    const int m_blk = wid & 3;          // rows [16*m_blk, 16*m_blk+16)
    const int half = wid >> 2;          // n8 blocks [13*half, ...)
    const int r = lane >> 2;            // fragment row 0..7
    const int c = lane & 3;             // fragment col-in-group

    // ---- Build tf32-split B fragments (once) ----
    {
        const float g = gamma[0];
        for (int idx = tid; idx < NBN * 2 * 32; idx += TPB) {
            const int nb = idx >> 6, kb = (idx >> 5) & 1, ln = idx & 31;
            const int n = nb * 8 + (ln >> 2);
            const int k0 = kb * 8 + (ln & 3), k1 = k0 + 4;
            float w0 = (n < OUTC)
                ? fmaf(g, W3[n * DICT + k0], W4[n * DICT + k0]) : 0.0f;
            float w1 = (n < OUTC)
                ? fmaf(g, W3[n * DICT + k1], W4[n * DICT + k1]) : 0.0f;
            uint32_t h0 = cvt_tf32(w0), h1 = cvt_tf32(w1);
            float4 v;
            v.x = __uint_as_float(h0);
            v.y = __uint_as_float(h1);
            v.z = __uint_as_float(cvt_tf32(w0 - __uint_as_float(h0)));
            v.w = __uint_as_float(cvt_tf32(w1 - __uint_as_float(h1)));
            bf8[nb][kb][ln] = v;
        }
        for (int idx = tid; idx < NBN * 32; idx += TPB) {
            const int nb = idx >> 5, ln = idx & 31;
            const int n = nb * 8 + (ln >> 2);
            const int k = 16 + (ln & 3);
            float w = (n < OUTC)
                ? fmaf(g, W3[n * DICT + k], W4[n * DICT + k]) : 0.0f;
            uint32_t h = cvt_tf32(w);
            float2 v;
            v.x = __uint_as_float(h);
            v.y = __uint_as_float(cvt_tf32(w - __uint_as_float(h)));
            bf4[nb][ln] = v;
        }
    }
    __syncthreads();   // the ONLY barrier; mainloop is barrier-free

    const int nbg0 = half * NBW;

    // ---- Per-warp x loads: 10 LDG.32 per thread per tile ----
    // row0 = t*64 + m_blk*16 + r ; values: [k=c, c+4, c+8, c+12, c+16] x
    // rows {row0, row0+8}.
    float xr[10];
    {
        const float* px =
            x + ((size_t)blockIdx.x * TILE + m_blk * 16 + r) * DICT;
        #pragma unroll
        for (int j = 0; j < 5; j++) {
            xr[2 * j]     = __ldg(px + c + 4 * j);
            xr[2 * j + 1] = __ldg(px + 160 + c + 4 * j);   // +8 rows
        }
    }

    for (int t = blockIdx.x; t < ntiles; t += NBLK) {
        // ---- tf32-split current x into A fragments ----
        uint32_t ah[10], al[10];
        #pragma unroll
        for (int j = 0; j < 10; j++) {
            ah[j] = cvt_tf32(xr[j]);
            al[j] = cvt_tf32(xr[j] - __uint_as_float(ah[j]));
        }

        // ---- Prefetch next tile's x (overlaps HMMA + epilogue below) ----
        const int tn = t + NBLK;
        if (tn < ntiles) {
            const float* px =
                x + ((size_t)tn * TILE + m_blk * 16 + r) * DICT;
            #pragma unroll
            for (int j = 0; j < 5; j++) {
                xr[2 * j]     = __ldg(px + c + 4 * j);
                xr[2 * j + 1] = __ldg(px + 160 + c + 4 * j);
            }
        }

        // ---- 13 n-blocks x (2 k8 + 1 k4) x 3 split terms ----
        float acc[NBW][4];
        #pragma unroll
        for (int nb = 0; nb < NBW; nb++) {
            acc[nb][0] = acc[nb][1] = acc[nb][2] = acc[nb][3] = 0.0f;
        }
        #pragma unroll
        for (int nb = 0; nb < NBW; nb++) {
            const float4 f0 = bf8[nbg0 + nb][0][lane];   // LDS.128
            const float4 f1 = bf8[nbg0 + nb][1][lane];
            const float2 f2 = bf4[nbg0 + nb][lane];      // LDS.64
            // xh * wh
            mma8(acc[nb], ah,     U(f0.x), U(f0.y));
            mma8(acc[nb], ah + 4, U(f1.x), U(f1.y));
            mma4(acc[nb], ah[8], ah[9], U(f2.x));
            // xh * wl
            mma8(acc[nb], ah,     U(f0.z), U(f0.w));
            mma8(acc[nb], ah + 4, U(f1.z), U(f1.w));
            mma4(acc[nb], ah[8], ah[9], U(f2.y));
            // xl * wh
            mma8(acc[nb], al,     U(f0.x), U(f0.y));
            mma8(acc[nb], al + 4, U(f1.x), U(f1.y));
            mma4(acc[nb], al[8], al[9], U(f2.x));
        }

        // ---- Epilogue: relu + STG.64 (rows r and r+8 of this fragment) ----
        {
            float* o0 = out + (size_t)(t * TILE + m_blk * 16 + r) * OUTC;
            float* o1 = o0 + 8 * OUTC;
            #pragma unroll
            for (int nb = 0; nb < NBW; nb++) {
                const int cb = half * 104 + nb * 8 + c * 2;
                if (cb < OUTC) {
                    *reinterpret_cast<float2*>(o0 + cb) =
                        make_float2(fmaxf(acc[nb][0], 0.0f),
                                    fmaxf(acc[nb][1], 0.0f));
                    *reinterpret_cast<float2*>(o1 + cb) =
                        make_float2(fmaxf(acc[nb][2], 0.0f),
                                    fmaxf(acc[nb][3], 0.0f));
                }
            }
        }
    }
}

extern "C" void kernel_launch(void* const* d_in, const int* in_sizes, int n_in,
                              void* d_out, int out_size) {
    const float* x     = (const float*)d_in[0];
    // d_in[1] = W1, d_in[2] = W2 : dead (softmax over size-1 axis == 1)
    const float* W3    = (const float*)d_in[3];
    const float* W4    = (const float*)d_in[4];
    const float* gamma = (const float*)d_in[5];
    float* out = (float*)d_out;

    const int B = in_sizes[0] / DICT;   // 262144
    const int ntiles = B / TILE;        // 4096 (exact)

    fused_gemm_relu_mma<<<NBLK, TPB>>>(x, W3, W4, gamma, out, ntiles);
}